// round 3
// baseline (speedup 1.0000x reference)
#include <cuda_runtime.h>
#include <math.h>

#define NN    8192
#define EE    262144
#define CC    64
#define ELLW  128   // Poisson(32) tail beyond 128 ~ 1e-40

// ---- scratch (__device__ globals) ----
__device__ int    g_cnt[NN];           // raw scatter counts
__device__ int    g_cnt2[NN];          // deduped counts
__device__ float  g_deg[NN];
__device__ int    g_ellc[NN * ELLW];   // raw: col
__device__ int    g_ellj[NN * ELLW];   // raw: edge id
__device__ float  g_ellw[NN * ELLW];   // raw: gated weight
__device__ float2 g_ell[NN * ELLW];    // packed winners: (col_as_float, w -> coef)
__device__ float  g_T1[NN * CC];
__device__ float  g_T2[NN * CC];
__device__ float  g_gate;
__device__ int    g_is32;

__device__ __forceinline__ void load_rc(const void* ei, int j, int& r, int& c) {
    if (g_is32) {
        const int* e = (const int*)ei;
        r = e[j]; c = e[EE + j];
    } else {
        const long long* e = (const long long*)ei;
        r = (int)e[j]; c = (int)e[EE + j];
    }
}

// 0) detect edge_index dtype (int32 vs int64) — one warp
__global__ void k_detect(const void* ei, const float* __restrict__ aw) {
    const long long* e64 = (const long long*)ei;
    int lane = threadIdx.x;
    long long v0 = e64[lane];
    long long v1 = e64[32 + lane];
    int bad = (v0 < 0 || v0 >= NN || v1 < 0 || v1 >= NN);
    unsigned any = __any_sync(0xffffffffu, bad);
    if (lane == 0) {
        g_is32 = any ? 1 : 0;
        g_gate = 1.0f / (1.0f + expf(-aw[0]));
    }
}

// 1) reset counters
__global__ void k_init() {
    int i = blockIdx.x * blockDim.x + threadIdx.x;
    if (i < NN) g_cnt[i] = 0;
}

// 2) scatter edges into per-row ELL lists (order nondeterministic; j recorded)
__global__ void k_scatter(const void* __restrict__ ei,
                          const float* __restrict__ ew) {
    int j = blockIdx.x * blockDim.x + threadIdx.x;
    if (j >= EE) return;
    int r, c; load_rc(ei, j, r, c);
    int pos = atomicAdd(&g_cnt[r], 1);
    if (pos < ELLW) {
        int idx = r * ELLW + pos;
        g_ellc[idx] = c;
        g_ellj[idx] = j;
        g_ellw[idx] = ew[j] * g_gate;
    }
}

// 3) per-row last-write-wins dedupe + degree + compaction. One warp per row.
__global__ void k_dedup() {
    __shared__ int   sc[8][ELLW];
    __shared__ int   sj[8][ELLW];
    __shared__ float sw[8][ELLW];
    int wid  = threadIdx.x >> 5;
    int lane = threadIdx.x & 31;
    int r = blockIdx.x * 8 + wid;

    int nnz = min(g_cnt[r], ELLW);
    for (int k = lane; k < nnz; k += 32) {
        int idx = r * ELLW + k;
        sc[wid][k] = g_ellc[idx];
        sj[wid][k] = g_ellj[idx];
        sw[wid][k] = g_ellw[idx];
    }
    __syncwarp();

    float degsum = 0.0f;
    int outpos = 0;
    for (int base = 0; base < nnz; base += 32) {
        int k = base + lane;
        bool alive = false;
        int c = 0; float wv = 0.0f;
        if (k < nnz) {
            c = sc[wid][k];
            int j = sj[wid][k];
            wv = sw[wid][k];
            alive = true;
            for (int m = 0; m < nnz; m++) {
                if (sc[wid][m] == c && sj[wid][m] > j) { alive = false; break; }
            }
        }
        unsigned bal = __ballot_sync(0xffffffffu, alive);
        int pos = outpos + __popc(bal & ((1u << lane) - 1u));
        if (alive) {
            g_ell[r * ELLW + pos] = make_float2(__int_as_float(c), wv);
            degsum += wv;
        }
        outpos += __popc(bal);
    }
    #pragma unroll
    for (int off = 16; off > 0; off >>= 1)
        degsum += __shfl_xor_sync(0xffffffffu, degsum, off);
    if (lane == 0) {
        g_cnt2[r] = outpos;
        g_deg[r]  = 1.0f + degsum;
    }
}

// 4) T1 = L x ; also rewrites g_ell[].y from weight -> final coefficient
__global__ void k_spmm1(const float* __restrict__ x) {
    int gtid = blockIdx.x * blockDim.x + threadIdx.x;
    int r = gtid >> 5;
    int lane = gtid & 31;

    const float2* x2 = (const float2*)x;
    float dr = g_deg[r];
    float sr = rsqrtf(dr);
    float diag = 1.0f - 1.0f / dr;

    float2 acc = x2[r * 32 + lane];
    acc.x *= diag; acc.y *= diag;

    int nnz = g_cnt2[r];
    int base = r * ELLW;
    #pragma unroll 4
    for (int k = 0; k < nnz; k++) {
        float2 e = g_ell[base + k];
        int c = __float_as_int(e.x);
        float coef = -sr * e.y * rsqrtf(g_deg[c]);
        if (lane == 0) g_ell[base + k].y = coef;   // cache for spmm2
        float2 zc = x2[c * 32 + lane];
        acc.x = fmaf(coef, zc.x, acc.x);
        acc.y = fmaf(coef, zc.y, acc.y);
    }
    ((float2*)g_T1)[r * 32 + lane] = acc;
}

// 5) T2 = 2 L T1 - x  (coefficients already final)
__global__ void k_spmm2(const float* __restrict__ x) {
    int gtid = blockIdx.x * blockDim.x + threadIdx.x;
    int r = gtid >> 5;
    int lane = gtid & 31;

    const float2* t1 = (const float2*)g_T1;
    float dr = g_deg[r];
    float diag = 1.0f - 1.0f / dr;

    float2 acc = t1[r * 32 + lane];
    acc.x *= diag; acc.y *= diag;

    int nnz = g_cnt2[r];
    int base = r * ELLW;
    #pragma unroll 4
    for (int k = 0; k < nnz; k++) {
        float2 e = g_ell[base + k];
        int c = __float_as_int(e.x);
        float2 zc = t1[c * 32 + lane];
        acc.x = fmaf(e.y, zc.x, acc.x);
        acc.y = fmaf(e.y, zc.y, acc.y);
    }
    float2 x0 = ((const float2*)x)[r * 32 + lane];
    acc.x = 2.0f * acc.x - x0.x;
    acc.y = 2.0f * acc.y - x0.y;
    ((float2*)g_T2)[r * 32 + lane] = acc;
}

// 6) fused output GEMM: out = x@W0 + T1@W1 + T2@W2 + bias
__global__ void k_out(const float* __restrict__ x,
                      const float* __restrict__ w,
                      const float* __restrict__ bias,
                      float* __restrict__ out) {
    __shared__ float ws[3 * 64 * 64];  // 48 KB
    int tid = threadIdx.x;
    for (int i = tid; i < 3 * 64 * 64; i += 256) ws[i] = w[i];
    __syncthreads();

    int o  = tid & 63;
    int ty = tid >> 6;
    int r0 = blockIdx.x * 64;
    float b = __ldg(&bias[o]);

    for (int rr = 0; rr < 16; rr++) {
        int r = r0 + rr * 4 + ty;
        const float* x0 = x    + r * 64;
        const float* t1 = g_T1 + r * 64;
        const float* t2 = g_T2 + r * 64;
        float acc = b;
        #pragma unroll 16
        for (int i = 0; i < 64; i++) {
            acc = fmaf(x0[i], ws[i * 64 + o],
                  fmaf(t1[i], ws[4096 + i * 64 + o],
                  fmaf(t2[i], ws[8192 + i * 64 + o], acc)));
        }
        out[r * 64 + o] = acc;
    }
}

extern "C" void kernel_launch(void* const* d_in, const int* in_sizes, int n_in,
                              void* d_out, int out_size) {
    const float* x    = (const float*)d_in[0];
    const void*  ei   = (const void*)d_in[1];
    const float* ew   = (const float*)d_in[2];
    const float* w    = (const float*)d_in[3];
    const float* aw   = (const float*)d_in[4];
    const float* bias = (const float*)d_in[5];
    float* out = (float*)d_out;

    k_detect <<<1, 32>>>(ei, aw);
    k_init   <<<NN / 256, 256>>>();
    k_scatter<<<EE / 256, 256>>>(ei, ew);
    k_dedup  <<<NN / 8, 256>>>();
    k_spmm1  <<<NN * 32 / 256, 256>>>(x);
    k_spmm2  <<<NN * 32 / 256, 256>>>(x);
    k_out    <<<NN / 64, 256>>>(x, w, bias, out);
}

// round 4
// speedup vs baseline: 3.0740x; 3.0740x over previous
#include <cuda_runtime.h>
#include <math.h>

#define NN    8192
#define EE    262144
#define CC    64
#define ELLW  128   // Poisson(32) tail beyond 128 ~ 1e-40

// ---- scratch (__device__ globals) ----
__device__ int    g_cnt[NN];           // raw scatter counts
__device__ int    g_cnt2[NN];          // deduped counts
__device__ float  g_deg[NN];
__device__ float  g_sinv[NN];          // rsqrt(deg)
__device__ int2   g_ellcj[NN * ELLW];  // raw: (col, edge id)
__device__ float2 g_ell[NN * ELLW];    // winners: (col_as_float, gated weight)
__device__ float  g_T1[NN * CC];
__device__ float  g_T2[NN * CC];
__device__ float  g_gate;
__device__ int    g_is32;

__device__ __forceinline__ void load_rc(const void* ei, int j, int& r, int& c) {
    if (g_is32) {
        const int* e = (const int*)ei;
        r = e[j]; c = e[EE + j];
    } else {
        const long long* e = (const long long*)ei;
        r = (int)e[j]; c = (int)e[EE + j];
    }
}

// 0) zero counters + dtype detect + gate (merged)
__global__ void k_setup(const void* ei, const float* __restrict__ aw) {
    int i = blockIdx.x * blockDim.x + threadIdx.x;
    if (i < NN) g_cnt[i] = 0;
    if (blockIdx.x == 0 && threadIdx.x < 32) {
        const long long* e64 = (const long long*)ei;
        int lane = threadIdx.x;
        long long v0 = e64[lane];
        long long v1 = e64[32 + lane];
        int bad = (v0 < 0 || v0 >= NN || v1 < 0 || v1 >= NN);
        unsigned any = __any_sync(0xffffffffu, bad);
        if (lane == 0) {
            g_is32 = any ? 1 : 0;
            g_gate = 1.0f / (1.0f + expf(-aw[0]));
        }
    }
}

// 1) scatter edges into per-row lists (order nondeterministic; j recorded)
__global__ void k_scatter(const void* __restrict__ ei) {
    int j = blockIdx.x * blockDim.x + threadIdx.x;
    if (j >= EE) return;
    int r, c; load_rc(ei, j, r, c);
    int pos = atomicAdd(&g_cnt[r], 1);
    if (pos < ELLW) g_ellcj[r * ELLW + pos] = make_int2(c, j);
}

// 2) per-row dedupe via 256-slot per-warp shared hash.
//    entry = (col+1)<<18 | j  -> atomicMax = last-write-wins on edge id.
__global__ void k_dedup(const float* __restrict__ ew) {
    __shared__ unsigned tab[8][256];
    int wid  = threadIdx.x >> 5;
    int lane = threadIdx.x & 31;
    #pragma unroll
    for (int i = 0; i < 8; i++) tab[wid][lane + 32 * i] = 0u;
    __syncwarp();

    int r = blockIdx.x * 8 + wid;
    int nnz = min(g_cnt[r], ELLW);

    for (int k = lane; k < nnz; k += 32) {
        int2 cj = g_ellcj[r * ELLW + k];
        unsigned c = (unsigned)cj.x;
        unsigned entry = ((c + 1u) << 18) | (unsigned)cj.y;
        unsigned h = (c * 2654435761u) >> 24;
        for (;;) {
            unsigned cur = tab[wid][h];
            if (cur == 0u) {
                unsigned old = atomicCAS(&tab[wid][h], 0u, entry);
                if (old == 0u) break;
                cur = old;
            }
            if ((cur >> 18) == c + 1u) { atomicMax(&tab[wid][h], entry); break; }
            h = (h + 1u) & 255u;
        }
    }
    __syncwarp();

    float gate = g_gate;
    float degsum = 0.0f;
    int outpos = 0;
    #pragma unroll
    for (int it = 0; it < 8; it++) {
        unsigned e = tab[wid][lane + 32 * it];
        bool alive = (e != 0u);
        int c = 0; float wv = 0.0f;
        if (alive) {
            c = (int)(e >> 18) - 1;
            int j = (int)(e & 0x3FFFFu);
            wv = ew[j] * gate;
            degsum += wv;
        }
        unsigned bal = __ballot_sync(0xffffffffu, alive);
        int pos = outpos + __popc(bal & ((1u << lane) - 1u));
        if (alive) g_ell[r * ELLW + pos] = make_float2(__int_as_float(c), wv);
        outpos += __popc(bal);
    }
    #pragma unroll
    for (int off = 16; off > 0; off >>= 1)
        degsum += __shfl_xor_sync(0xffffffffu, degsum, off);
    if (lane == 0) {
        float d = 1.0f + degsum;
        g_cnt2[r] = outpos;
        g_deg[r]  = d;
        g_sinv[r] = rsqrtf(d);
    }
}

// 3/4) SpMM: mode 1: T1 = L x ; mode 2: T2 = 2 L T1 - x
// one warp per row; each lane owns 2 channels (float2)
__global__ void k_spmm(const float* __restrict__ x, int mode) {
    int gtid = blockIdx.x * blockDim.x + threadIdx.x;
    int r = gtid >> 5;
    int lane = gtid & 31;

    const float2* z2 = (mode == 1) ? (const float2*)x : (const float2*)g_T1;
    float dr = g_deg[r];
    float sr = g_sinv[r];
    float diag = 1.0f - 1.0f / dr;

    float2 acc = z2[r * 32 + lane];
    acc.x *= diag; acc.y *= diag;

    int nnz = g_cnt2[r];
    int base = r * ELLW;
    #pragma unroll 4
    for (int k = 0; k < nnz; k++) {
        float2 e = g_ell[base + k];
        int c = __float_as_int(e.x);
        float coef = -sr * e.y * g_sinv[c];
        float2 zc = z2[c * 32 + lane];
        acc.x = fmaf(coef, zc.x, acc.x);
        acc.y = fmaf(coef, zc.y, acc.y);
    }

    if (mode == 1) {
        ((float2*)g_T1)[r * 32 + lane] = acc;
    } else {
        float2 x0 = ((const float2*)x)[r * 32 + lane];
        acc.x = 2.0f * acc.x - x0.x;
        acc.y = 2.0f * acc.y - x0.y;
        ((float2*)g_T2)[r * 32 + lane] = acc;
    }
}

// 5) fused output GEMM: out = x@W0 + T1@W1 + T2@W2 + bias
// grid 256 blocks, 32 rows/block; thread (o, ty) owns 8 rows x 1 out-channel
__global__ void k_out(const float* __restrict__ x,
                      const float* __restrict__ w,
                      const float* __restrict__ bias,
                      float* __restrict__ out) {
    __shared__ float ws[64 * 64];   // current W_m (16 KB)
    __shared__ float ts[32 * 64];   // 32-row tile of T_m (8 KB)
    int tid = threadIdx.x;
    int o  = tid & 63;
    int ty = tid >> 6;              // 0..3
    int r0 = blockIdx.x * 32;

    float b = __ldg(&bias[o]);
    float acc[8];
    #pragma unroll
    for (int q = 0; q < 8; q++) acc[q] = b;

    const float* mats[3];
    mats[0] = x    + r0 * 64;
    mats[1] = g_T1 + r0 * 64;
    mats[2] = g_T2 + r0 * 64;

    for (int m = 0; m < 3; m++) {
        for (int idx = tid; idx < 4096; idx += 256) ws[idx] = w[m * 4096 + idx];
        const float4* src = (const float4*)mats[m];
        float4* dst = (float4*)ts;
        for (int idx = tid; idx < 32 * 16; idx += 256) dst[idx] = src[idx];
        __syncthreads();

        #pragma unroll 2
        for (int i4 = 0; i4 < 16; i4++) {
            float w0 = ws[(i4 * 4 + 0) * 64 + o];
            float w1 = ws[(i4 * 4 + 1) * 64 + o];
            float w2 = ws[(i4 * 4 + 2) * 64 + o];
            float w3 = ws[(i4 * 4 + 3) * 64 + o];
            #pragma unroll
            for (int q = 0; q < 8; q++) {
                float4 tv = ((const float4*)(ts + (ty * 8 + q) * 64))[i4];
                acc[q] = fmaf(tv.x, w0, fmaf(tv.y, w1,
                         fmaf(tv.z, w2, fmaf(tv.w, w3, acc[q]))));
            }
        }
        __syncthreads();
    }
    #pragma unroll
    for (int q = 0; q < 8; q++)
        out[(r0 + ty * 8 + q) * 64 + o] = acc[q];
}

extern "C" void kernel_launch(void* const* d_in, const int* in_sizes, int n_in,
                              void* d_out, int out_size) {
    const float* x    = (const float*)d_in[0];
    const void*  ei   = (const void*)d_in[1];
    const float* ew   = (const float*)d_in[2];
    const float* w    = (const float*)d_in[3];
    const float* aw   = (const float*)d_in[4];
    const float* bias = (const float*)d_in[5];
    float* out = (float*)d_out;

    k_setup  <<<NN / 256, 256>>>(ei, aw);
    k_scatter<<<EE / 256, 256>>>(ei);
    k_dedup  <<<NN / 8, 256>>>(ew);
    k_spmm   <<<NN * 32 / 256, 256>>>(x, 1);   // T1 = L x
    k_spmm   <<<NN * 32 / 256, 256>>>(x, 2);   // T2 = 2 L T1 - x
    k_out    <<<NN / 32, 256>>>(x, w, bias, out);
}

// round 5
// speedup vs baseline: 3.2057x; 1.0428x over previous
#include <cuda_runtime.h>
#include <math.h>

#define NN    8192
#define EE    262144
#define CC    64
#define ELLW  128   // Poisson(32) tail beyond 128 ~ 1e-40

// ---- scratch (__device__ globals) ----
__device__ int    g_cnt[NN];           // raw scatter counts
__device__ int    g_cnt2[NN];          // deduped counts
__device__ float  g_deg[NN];
__device__ float  g_sinv[NN];          // rsqrt(deg)
__device__ int2   g_ellcj[NN * ELLW];  // raw: (col, edge id)
__device__ float2 g_ell[NN * ELLW];    // winners: (col_as_float, w -> coef)
__device__ float  g_T1[NN * CC];
__device__ float  g_T2[NN * CC];
__device__ float  g_gate;
__device__ int    g_is32;

__device__ __forceinline__ void load_rc(const void* ei, int j, int& r, int& c) {
    if (g_is32) {
        const int* e = (const int*)ei;
        r = e[j]; c = e[EE + j];
    } else {
        const long long* e = (const long long*)ei;
        r = (int)e[j]; c = (int)e[EE + j];
    }
}

// 0) zero counters + dtype detect + gate (merged)
__global__ void k_setup(const void* ei, const float* __restrict__ aw) {
    int i = blockIdx.x * blockDim.x + threadIdx.x;
    if (i < NN) g_cnt[i] = 0;
    if (blockIdx.x == 0 && threadIdx.x < 32) {
        const long long* e64 = (const long long*)ei;
        int lane = threadIdx.x;
        long long v0 = e64[lane];
        long long v1 = e64[32 + lane];
        int bad = (v0 < 0 || v0 >= NN || v1 < 0 || v1 >= NN);
        unsigned any = __any_sync(0xffffffffu, bad);
        if (lane == 0) {
            g_is32 = any ? 1 : 0;
            g_gate = 1.0f / (1.0f + expf(-aw[0]));
        }
    }
}

// 1) scatter edges into per-row lists (order nondeterministic; j recorded)
__global__ void k_scatter(const void* __restrict__ ei) {
    int j = blockIdx.x * blockDim.x + threadIdx.x;
    if (j >= EE) return;
    int r, c; load_rc(ei, j, r, c);
    int pos = atomicAdd(&g_cnt[r], 1);
    if (pos < ELLW) g_ellcj[r * ELLW + pos] = make_int2(c, j);
}

// 2) per-row dedupe via 256-slot per-warp shared hash.
//    entry = (col+1)<<18 | j  -> atomicMax = last-write-wins on edge id.
__global__ void k_dedup(const float* __restrict__ ew) {
    __shared__ unsigned tab[8][256];
    int wid  = threadIdx.x >> 5;
    int lane = threadIdx.x & 31;
    #pragma unroll
    for (int i = 0; i < 8; i++) tab[wid][lane + 32 * i] = 0u;
    __syncwarp();

    int r = blockIdx.x * 8 + wid;
    int nnz = min(g_cnt[r], ELLW);

    for (int k = lane; k < nnz; k += 32) {
        int2 cj = g_ellcj[r * ELLW + k];
        unsigned c = (unsigned)cj.x;
        unsigned entry = ((c + 1u) << 18) | (unsigned)cj.y;
        unsigned h = (c * 2654435761u) >> 24;
        for (;;) {
            unsigned cur = tab[wid][h];
            if (cur == 0u) {
                unsigned old = atomicCAS(&tab[wid][h], 0u, entry);
                if (old == 0u) break;
                cur = old;
            }
            if ((cur >> 18) == c + 1u) { atomicMax(&tab[wid][h], entry); break; }
            h = (h + 1u) & 255u;
        }
    }
    __syncwarp();

    float gate = g_gate;
    float degsum = 0.0f;
    int outpos = 0;
    #pragma unroll
    for (int it = 0; it < 8; it++) {
        unsigned e = tab[wid][lane + 32 * it];
        bool alive = (e != 0u);
        int c = 0; float wv = 0.0f;
        if (alive) {
            c = (int)(e >> 18) - 1;
            int j = (int)(e & 0x3FFFFu);
            wv = __ldg(&ew[j]) * gate;
            degsum += wv;
        }
        unsigned bal = __ballot_sync(0xffffffffu, alive);
        int pos = outpos + __popc(bal & ((1u << lane) - 1u));
        if (alive) g_ell[r * ELLW + pos] = make_float2(__int_as_float(c), wv);
        outpos += __popc(bal);
    }
    #pragma unroll
    for (int off = 16; off > 0; off >>= 1)
        degsum += __shfl_xor_sync(0xffffffffu, degsum, off);
    if (lane == 0) {
        float d = 1.0f + degsum;
        g_cnt2[r] = outpos;
        g_deg[r]  = d;
        g_sinv[r] = rsqrtf(d);
    }
}

// 3) finalize coefficients: g_ell[].y = -sinv[r] * w * sinv[c]
//    one warp per row, lanes stride entries
__global__ void k_coef() {
    int gtid = blockIdx.x * blockDim.x + threadIdx.x;
    int r = gtid >> 5;
    int lane = gtid & 31;
    int nnz = g_cnt2[r];
    float sr = g_sinv[r];
    int base = r * ELLW;
    for (int k = lane; k < nnz; k += 32) {
        float2 e = g_ell[base + k];
        int c = __float_as_int(e.x);
        g_ell[base + k].y = -sr * e.y * __ldg(&g_sinv[c]);
    }
}

// 4/5) SpMM: mode 1: T1 = L x ; mode 2: T2 = 2 L T1 - x
// one warp per row; each lane owns 2 channels (float2)
__global__ void k_spmm(const float* __restrict__ x, int mode) {
    int gtid = blockIdx.x * blockDim.x + threadIdx.x;
    int r = gtid >> 5;
    int lane = gtid & 31;

    const float2* __restrict__ z2 =
        (mode == 1) ? (const float2*)x : (const float2*)g_T1;
    float dr = g_deg[r];
    float diag = 1.0f - 1.0f / dr;

    float2 acc = __ldg(&z2[r * 32 + lane]);
    acc.x *= diag; acc.y *= diag;

    int nnz = g_cnt2[r];
    const float2* __restrict__ ell = g_ell + r * ELLW;
    #pragma unroll 8
    for (int k = 0; k < nnz; k++) {
        float2 e = __ldg(&ell[k]);
        int c = __float_as_int(e.x);
        float2 zc = __ldg(&z2[c * 32 + lane]);
        acc.x = fmaf(e.y, zc.x, acc.x);
        acc.y = fmaf(e.y, zc.y, acc.y);
    }

    if (mode == 1) {
        ((float2*)g_T1)[r * 32 + lane] = acc;
    } else {
        float2 x0 = __ldg(&((const float2*)x)[r * 32 + lane]);
        acc.x = 2.0f * acc.x - x0.x;
        acc.y = 2.0f * acc.y - x0.y;
        ((float2*)g_T2)[r * 32 + lane] = acc;
    }
}

// 6) fused output GEMM: out = x@W0 + T1@W1 + T2@W2 + bias
__global__ void k_out(const float* __restrict__ x,
                      const float* __restrict__ w,
                      const float* __restrict__ bias,
                      float* __restrict__ out) {
    __shared__ float ws[64 * 64];   // current W_m (16 KB)
    __shared__ float ts[32 * 64];   // 32-row tile of T_m (8 KB)
    int tid = threadIdx.x;
    int o  = tid & 63;
    int ty = tid >> 6;              // 0..3
    int r0 = blockIdx.x * 32;

    float b = __ldg(&bias[o]);
    float acc[8];
    #pragma unroll
    for (int q = 0; q < 8; q++) acc[q] = b;

    const float* mats[3];
    mats[0] = x    + r0 * 64;
    mats[1] = g_T1 + r0 * 64;
    mats[2] = g_T2 + r0 * 64;

    for (int m = 0; m < 3; m++) {
        for (int idx = tid; idx < 4096; idx += 256) ws[idx] = w[m * 4096 + idx];
        const float4* src = (const float4*)mats[m];
        float4* dst = (float4*)ts;
        for (int idx = tid; idx < 32 * 16; idx += 256) dst[idx] = src[idx];
        __syncthreads();

        #pragma unroll 2
        for (int i4 = 0; i4 < 16; i4++) {
            float w0 = ws[(i4 * 4 + 0) * 64 + o];
            float w1 = ws[(i4 * 4 + 1) * 64 + o];
            float w2 = ws[(i4 * 4 + 2) * 64 + o];
            float w3 = ws[(i4 * 4 + 3) * 64 + o];
            #pragma unroll
            for (int q = 0; q < 8; q++) {
                float4 tv = ((const float4*)(ts + (ty * 8 + q) * 64))[i4];
                acc[q] = fmaf(tv.x, w0, fmaf(tv.y, w1,
                         fmaf(tv.z, w2, fmaf(tv.w, w3, acc[q]))));
            }
        }
        __syncthreads();
    }
    #pragma unroll
    for (int q = 0; q < 8; q++)
        out[(r0 + ty * 8 + q) * 64 + o] = acc[q];
}

extern "C" void kernel_launch(void* const* d_in, const int* in_sizes, int n_in,
                              void* d_out, int out_size) {
    const float* x    = (const float*)d_in[0];
    const void*  ei   = (const void*)d_in[1];
    const float* ew   = (const float*)d_in[2];
    const float* w    = (const float*)d_in[3];
    const float* aw   = (const float*)d_in[4];
    const float* bias = (const float*)d_in[5];
    float* out = (float*)d_out;

    k_setup  <<<NN / 256, 256>>>(ei, aw);
    k_scatter<<<EE / 256, 256>>>(ei);
    k_dedup  <<<NN / 8, 256>>>(ew);
    k_coef   <<<NN * 32 / 256, 256>>>();
    k_spmm   <<<NN * 32 / 256, 256>>>(x, 1);   // T1 = L x
    k_spmm   <<<NN * 32 / 256, 256>>>(x, 2);   // T2 = 2 L T1 - x
    k_out    <<<NN / 32, 256>>>(x, w, bias, out);
}